// round 14
// baseline (speedup 1.0000x reference)
#include <cuda_runtime.h>
#include <cuda_bf16.h>
#include <cstdint>
#include <cstddef>

// EntmaxAttention, fp32 [B=2,H=16,S=2048,D=64], T=8.  mma.sync m16n8k16 bf16.
//
// R13 = R12 resubmission (broker timeout, never measured):
// broken accumulator chains — the 12 HMMAs per chunk were a strict 12-deep
// RAW chain on one accumulator quad; now 3 independent products (AhBh, AlBh,
// AhBl) accumulate into D1/D2/D3 (chains of 4) and combine with 8 FADDs.
// K fragments precomputed once (kfrag_prep) in per-lane MMA order.
// Phase 2/3: warp-per-row Michelot sparsemax + sparse AV gather (proven).

#define TQ      16
#define SEQ     2048
#define DIM     64
#define CH      128
#define NCHUNK  (SEQ / CH)        // 16
#define THREADS 512
#define NBH     32                // B*H fixed for this problem
#define SSTR    2052              // score row stride (floats)

#define SM_SSC  0                                   // 16*2052*4 = 131328
#define SM_QF   131328                              // 16*64*4 = 4096
#define SMEM_TOTAL (SM_QF + 4096)                   // 135424

// B-fragment buffer: [bh][chunk][warp][lane] x 4 uint4 (16 words: 8 hi, 8 lo).
__device__ __align__(16) uint4 g_kfrag[NBH * NCHUNK * 16 * 32 * 4];

static __device__ __forceinline__ uint32_t pack2(__nv_bfloat16 x, __nv_bfloat16 y) {
    return (uint32_t)__bfloat16_as_ushort(x) | ((uint32_t)__bfloat16_as_ushort(y) << 16);
}

static __device__ __forceinline__ void mma16816(float* d, const uint32_t* a,
                                                uint32_t b0, uint32_t b1) {
    asm volatile(
        "mma.sync.aligned.m16n8k16.row.col.f32.bf16.bf16.f32 "
        "{%0,%1,%2,%3}, {%4,%5,%6,%7}, {%8,%9}, {%0,%1,%2,%3};"
        : "+f"(d[0]), "+f"(d[1]), "+f"(d[2]), "+f"(d[3])
        : "r"(a[0]), "r"(a[1]), "r"(a[2]), "r"(a[3]), "r"(b0), "r"(b1));
}

static __device__ __forceinline__ void split2(float x, __nv_bfloat16& h, __nv_bfloat16& l) {
    h = __float2bfloat16_rn(x);
    l = __float2bfloat16_rn(x - __bfloat162float(h));
}

// Pre-pass: one thread per (bh, chunk, warp, lane) B-fragment row.
__global__ void kfrag_prep(const float* __restrict__ K) {
    int id = blockIdx.x * 256 + threadIdx.x;        // 0 .. 262143
    int lane  = id & 31;
    int warpid = (id >> 5) & 15;
    int chunk = (id >> 9) & 15;
    int bh    = id >> 13;
    int key = chunk * CH + warpid * 8 + (lane >> 2);
    int t = lane & 3;
    const float* kr = K + ((size_t)bh * SEQ + key) * DIM;

    uint32_t w[16];
    #pragma unroll
    for (int k0 = 0; k0 < 4; ++k0) {
        int d0 = 16 * k0 + 2 * t;
        float2 p0 = *reinterpret_cast<const float2*>(kr + d0);
        float2 p1 = *reinterpret_cast<const float2*>(kr + d0 + 8);
        __nv_bfloat16 h0,l0,h1,l1,h2,l2,h3,l3;
        split2(p0.x, h0, l0); split2(p0.y, h1, l1);
        split2(p1.x, h2, l2); split2(p1.y, h3, l3);
        w[2*k0]     = pack2(h0, h1);   // key-row word 8k0+t   (b0h)
        w[2*k0 + 1] = pack2(h2, h3);   // key-row word 8k0+t+4 (b1h)
        w[8 + 2*k0]     = pack2(l0, l1);
        w[8 + 2*k0 + 1] = pack2(l2, l3);
    }
    uint4* dst = g_kfrag + (size_t)id * 4;
    dst[0] = make_uint4(w[0],  w[1],  w[2],  w[3]);
    dst[1] = make_uint4(w[4],  w[5],  w[6],  w[7]);
    dst[2] = make_uint4(w[8],  w[9],  w[10], w[11]);
    dst[3] = make_uint4(w[12], w[13], w[14], w[15]);
}

__global__ __launch_bounds__(THREADS, 1)
void entmax_attn_kernel(const float* __restrict__ Q, const float* __restrict__ K,
                        const float* __restrict__ V, float* __restrict__ O)
{
    extern __shared__ char smem[];
    float* ssc = reinterpret_cast<float*>(smem + SM_SSC);
    float* qf  = reinterpret_cast<float*>(smem + SM_QF);

    const int bh = blockIdx.y;
    const int q0 = blockIdx.x * TQ;
    const float* Qb = Q + ((size_t)bh * SEQ + q0) * DIM;
    const float* Vb = V + (size_t)bh * SEQ * DIM;
    float*       Ob = O + ((size_t)bh * SEQ + q0) * DIM;

    const int tid  = threadIdx.x;
    const int wid  = tid >> 5;
    const int lane = tid & 31;
    const int g    = lane >> 2;
    const int t    = lane & 3;

    for (int i = tid; i < TQ * DIM; i += THREADS)
        qf[i] = Qb[i] * 0.125f;
    __syncthreads();

    // Persistent A fragments (Qh, Ql) for 4 k-steps.
    uint32_t Ah[4][4], Al[4][4];
    #pragma unroll
    for (int k0 = 0; k0 < 4; ++k0) {
        int c = 2 * t + 16 * k0;
        float e[8] = { qf[g*DIM + c],       qf[g*DIM + c + 1],
                       qf[(g+8)*DIM + c],   qf[(g+8)*DIM + c + 1],
                       qf[g*DIM + c + 8],   qf[g*DIM + c + 9],
                       qf[(g+8)*DIM + c+8], qf[(g+8)*DIM + c + 9] };
        __nv_bfloat16 h[8], l[8];
        #pragma unroll
        for (int i = 0; i < 8; ++i) split2(e[i], h[i], l[i]);
        Ah[k0][0] = pack2(h[0], h[1]); Ah[k0][1] = pack2(h[2], h[3]);
        Ah[k0][2] = pack2(h[4], h[5]); Ah[k0][3] = pack2(h[6], h[7]);
        Al[k0][0] = pack2(l[0], l[1]); Al[k0][1] = pack2(l[2], l[3]);
        Al[k0][2] = pack2(l[4], l[5]); Al[k0][3] = pack2(l[6], l[7]);
    }

    // ---------------- Phase 1: QK^T, fragments streamed from L2 ----------------
    const uint4* fb = g_kfrag + ((size_t)((bh * NCHUNK) * 16 + wid) * 32 + lane) * 4;
    const size_t cstride = (size_t)16 * 32 * 4;     // uint4 per chunk

    uint4 c0 = fb[0], c1 = fb[1], c2 = fb[2], c3 = fb[3];
    for (int c = 0; c < NCHUNK; ++c) {
        uint4 n0, n1, n2, n3;
        if (c + 1 < NCHUNK) {
            const uint4* nf = fb + (size_t)(c + 1) * cstride;
            n0 = nf[0]; n1 = nf[1]; n2 = nf[2]; n3 = nf[3];
        }

        // Three independent accumulator chains (4 MMAs each) instead of one
        // 12-deep RAW chain.
        float D1[4] = {0.f,0.f,0.f,0.f};     // Ah * Bh
        float D2[4] = {0.f,0.f,0.f,0.f};     // Al * Bh
        float D3[4] = {0.f,0.f,0.f,0.f};     // Ah * Bl
        // k0=0
        mma16816(D1, Ah[0], c0.x, c0.y);
        mma16816(D2, Al[0], c0.x, c0.y);
        mma16816(D3, Ah[0], c2.x, c2.y);
        // k0=1
        mma16816(D1, Ah[1], c0.z, c0.w);
        mma16816(D2, Al[1], c0.z, c0.w);
        mma16816(D3, Ah[1], c2.z, c2.w);
        // k0=2
        mma16816(D1, Ah[2], c1.x, c1.y);
        mma16816(D2, Al[2], c1.x, c1.y);
        mma16816(D3, Ah[2], c3.x, c3.y);
        // k0=3
        mma16816(D1, Ah[3], c1.z, c1.w);
        mma16816(D2, Al[3], c1.z, c1.w);
        mma16816(D3, Ah[3], c3.z, c3.w);

        float d0 = D1[0] + D2[0] + D3[0];
        float d1 = D1[1] + D2[1] + D3[1];
        float d2 = D1[2] + D2[2] + D3[2];
        float d3 = D1[3] + D2[3] + D3[3];

        const int col = c * CH + wid * 8 + 2 * t;
        *reinterpret_cast<float2*>(ssc + (size_t)g * SSTR + col)       = make_float2(d0, d1);
        *reinterpret_cast<float2*>(ssc + (size_t)(g + 8) * SSTR + col) = make_float2(d2, d3);

        c0 = n0; c1 = n1; c2 = n2; c3 = n3;
    }
    __syncthreads();

    // ---------------- Phase 2+3: sparsemax + sparse AV ----------------
    const int r = wid;
    float sreg[64];
    const float* srow = ssc + (size_t)r * SSTR;
    #pragma unroll
    for (int j = 0; j < 64; ++j) sreg[j] = srow[j * 32 + lane];

    float m = sreg[0];
    #pragma unroll
    for (int j = 1; j < 64; ++j) m = fmaxf(m, sreg[j]);
    #pragma unroll
    for (int off = 16; off; off >>= 1)
        m = fmaxf(m, __shfl_xor_sync(0xffffffffu, m, off));

    float tau = m - 1.0f;
    for (int it = 0; it < 32; ++it) {
        float ssum = 0.0f, cntf = 0.0f;
        #pragma unroll
        for (int j = 0; j < 64; ++j) {
            if (sreg[j] > tau) { ssum += sreg[j]; cntf += 1.0f; }
        }
        #pragma unroll
        for (int off = 16; off; off >>= 1) {
            ssum += __shfl_xor_sync(0xffffffffu, ssum, off);
            cntf += __shfl_xor_sync(0xffffffffu, cntf, off);
        }
        float nt = (ssum - 1.0f) / cntf;
        if (nt == tau) break;
        tau = nt;
    }

    float o0 = 0.0f, o1 = 0.0f;
    #pragma unroll
    for (int j = 0; j < 64; ++j) {
        float p = sreg[j] - tau;
        unsigned mset = __ballot_sync(0xffffffffu, p > 0.0f);
        while (mset) {
            int b = __ffs(mset) - 1;
            mset &= mset - 1;
            float pb = __shfl_sync(0xffffffffu, p, b);
            const float* vr = Vb + (size_t)(j * 32 + b) * DIM;
            o0 += pb * vr[lane];
            o1 += pb * vr[lane + 32];
        }
    }
    Ob[(size_t)r * DIM + lane]      = o0;
    Ob[(size_t)r * DIM + lane + 32] = o1;
}

extern "C" void kernel_launch(void* const* d_in, const int* in_sizes, int n_in,
                              void* d_out, int out_size)
{
    const float* q = (const float*)d_in[0];
    const float* k = (const float*)d_in[1];
    const float* v = (const float*)d_in[2];
    float*       o = (float*)d_out;

    const int BH = in_sizes[0] / (SEQ * DIM);   // 32

    kfrag_prep<<<(NBH * NCHUNK * 16 * 32) / 256, 256>>>(k);

    cudaFuncSetAttribute(entmax_attn_kernel,
                         cudaFuncAttributeMaxDynamicSharedMemorySize, SMEM_TOTAL);
    dim3 grid(SEQ / TQ, BH);
    entmax_attn_kernel<<<grid, THREADS, SMEM_TOTAL>>>(q, k, v, o);
}